// round 14
// baseline (speedup 1.0000x reference)
#include <cuda_runtime.h>
#include <cuda_bf16.h>
#include <cstdint>
#include <math.h>

// ---------------------------------------------------------------------------
// HybridQCNNQLSTM : B=256, S=1024, H=256
//   Stage 1: per-element MLP 1->16->16->12->8->4->4 (tanh) -> 1 (linear)
//   Stage 2: LSTM via mma.sync m16n8k16 bf16 (hi/lo split x3, fp32 acc)
//            8 clusters x 8 CTAs, TWO warp-specialized streams per CTA.
//            st.async DSMEM exchange with mbarrier complete_tx.
//            NEW: permuted A layout (row = h2*4+gate, paired K order) so the
//            epilogue runs in the MMA warps via shfl butterfly — zero
//            intra-CTA barriers per step, no smem gate transpose.
//   out = [cnn_features (B*S) | logits (B)]
// ---------------------------------------------------------------------------

#define BATCH 256
#define SEQ   1024
#define HID   256

// ======================= Stage 1: CNN MLP kernel ===========================

template<int DIN, int DOUT>
__device__ __forceinline__ void layer_tanh(const float* __restrict__ w,
                                           const float* __restrict__ b,
                                           const float* in, float* out) {
#pragma unroll
    for (int o = 0; o < DOUT; ++o) {
        float s = b[o];
#pragma unroll
        for (int i = 0; i < DIN; ++i) s = fmaf(w[o * DIN + i], in[i], s);
        out[o] = tanhf(s);
    }
}

__global__ void __launch_bounds__(256) cnn_kernel(
    const float* __restrict__ x,
    const float* __restrict__ w1, const float* __restrict__ b1,
    const float* __restrict__ w2, const float* __restrict__ b2,
    const float* __restrict__ w3, const float* __restrict__ b3,
    const float* __restrict__ w4, const float* __restrict__ b4,
    const float* __restrict__ w5, const float* __restrict__ b5,
    const float* __restrict__ w6, const float* __restrict__ b6,
    const float* __restrict__ w7, const float* __restrict__ b7,
    float* __restrict__ out)
{
    __shared__ float ws[673];
    const int tid = threadIdx.x;
    {
        const float* srcs[14] = {w1,b1,w2,b2,w3,b3,w4,b4,w5,b5,w6,b6,w7,b7};
        const int    lens[14] = {16,16,256,16,192,12,96,8,32,4,16,4,4,1};
        int off = 0;
        for (int s = 0; s < 14; ++s) {
            for (int i = tid; i < lens[s]; i += 256) ws[off + i] = srcs[s][i];
            off += lens[s];
        }
    }
    __syncthreads();

    const int e = blockIdx.x * 256 + tid;
    float v = x[e];
    float h1[16], h2[16], h3[12], h4[8], h5[4], h6[4];
    layer_tanh<1, 16>(ws + 0,   ws + 16,  &v, h1);
    layer_tanh<16,16>(ws + 32,  ws + 288, h1, h2);
    layer_tanh<16,12>(ws + 304, ws + 496, h2, h3);
    layer_tanh<12, 8>(ws + 508, ws + 604, h3, h4);
    layer_tanh<8,  4>(ws + 612, ws + 644, h4, h5);
    layer_tanh<4,  4>(ws + 648, ws + 664, h5, h6);
    float o = ws[672];
#pragma unroll
    for (int i = 0; i < 4; ++i) o = fmaf(ws[668 + i], h6[i], o);
    out[e] = o;
}

// ======================= Stage 2: LSTM (dual-stream, shuffle epi) ==========

#define NB           16                     // batches per stream
#define NCLUST       8
#define LSTM_CTAS    64
#define LSTM_THREADS 512

#define ROW_BYTES   1088                    // 16 kc * 64B + 64B pad
#define BIMG_BYTES  (NB * ROW_BYTES)        // 17408
#define TX_BYTES    16384u                  // real data per image per phase

// smem byte offsets
#define ALO_OFF    0                        // A-lo frags: 8*16*32*16 = 65536
#define BIMG_OFF   65536                    // 4 images (sid*2+buf) = 69632
#define WXB_OFF    153600                   // [4][32] f32
#define BIAS_OFF   154112
#define MBAR_OFF   154752                   // 4 x 8B
#define SMEM_BYTES 154880

__device__ float g_hxf32[BATCH * HID];

__device__ __forceinline__ float fast_sigmoid(float v) {
    return __fdividef(1.0f, 1.0f + __expf(-v));
}
__device__ __forceinline__ float fast_tanh(float v) {
    return 1.0f - __fdividef(2.0f, __expf(2.0f * v) + 1.0f);
}
__device__ __forceinline__ uint32_t pack2bf(float lo, float hi) {
    __nv_bfloat162 t = __floats2bfloat162_rn(lo, hi);
    return *(uint32_t*)&t;
}

__device__ __forceinline__ void mma16816(float* c, const uint32_t* a,
                                         uint32_t b0, uint32_t b1) {
    asm volatile(
        "mma.sync.aligned.m16n8k16.row.col.f32.bf16.bf16.f32 "
        "{%0,%1,%2,%3}, {%4,%5,%6,%7}, {%8,%9}, {%0,%1,%2,%3};"
        : "+f"(c[0]), "+f"(c[1]), "+f"(c[2]), "+f"(c[3])
        : "r"(a[0]), "r"(a[1]), "r"(a[2]), "r"(a[3]), "r"(b0), "r"(b1));
}

#define CLUSTER_SYNC_() do { \
    asm volatile("barrier.cluster.arrive.aligned;" ::: "memory"); \
    asm volatile("barrier.cluster.wait.aligned;"   ::: "memory"); \
} while (0)

#define FENCE_CLUSTER_() asm volatile("fence.acq_rel.cluster;" ::: "memory")

#define MBARRIER_INIT(mbar, cnt) \
    asm volatile("mbarrier.init.shared.b64 [%0], %1;" \
        :: "r"((uint32_t)(mbar)), "r"((uint32_t)(cnt)) : "memory")

#define MBAR_EXPECT_TX(mbar, bytes) \
    asm volatile("mbarrier.arrive.expect_tx.shared.b64 _, [%0], %1;" \
        :: "r"((uint32_t)(mbar)), "r"((uint32_t)(bytes)) : "memory")

#define MBAR_WAIT_PARITY(mbar, par) do { \
    uint32_t _m = (uint32_t)(mbar); uint32_t _p = (uint32_t)(par); uint32_t _d; \
    asm volatile("{\n\t.reg .pred p;\n\t" \
        "mbarrier.try_wait.parity.acquire.cta.shared::cta.b64 p, [%1], %2;\n\t" \
        "selp.b32 %0, 1, 0, p;\n\t}" : "=r"(_d) : "r"(_m), "r"(_p) : "memory"); \
    if (!_d) { \
        asm volatile("{\n\t.reg .pred P1;\n\t" \
            "WL_%=:\n\t" \
            "mbarrier.try_wait.parity.acquire.cta.shared::cta.b64 P1, [%0], %1, 0x989680;\n\t" \
            "@P1 bra.uni WD_%=;\n\t" \
            "bra.uni WL_%=;\n\t" \
            "WD_%=:\n\t}" :: "r"(_m), "r"(_p) : "memory"); \
    } \
} while(0)

// async DSMEM store: 8B payload + transaction completion on remote mbarrier
#define ST_ASYNC_B64(daddr, val, mbaddr) \
    asm volatile("st.async.weak.shared::cluster.mbarrier::complete_tx::bytes.b64 [%0], %1, [%2];" \
        :: "r"((uint32_t)(daddr)), "l"(val), "r"((uint32_t)(mbaddr)) : "memory")

__global__ void __launch_bounds__(LSTM_THREADS, 1) __cluster_dims__(8, 1, 1)
lstm_kernel(const float* __restrict__ xfeat,
            const float* __restrict__ w_f, const float* __restrict__ b_f,
            const float* __restrict__ w_i, const float* __restrict__ b_i,
            const float* __restrict__ w_g, const float* __restrict__ b_g,
            const float* __restrict__ w_o, const float* __restrict__ b_o,
            const float* __restrict__ w_head, const float* __restrict__ b_head,
            float* __restrict__ logits)
{
    extern __shared__ __align__(16) uint8_t sm8[];
    float* wxb_sm  = (float*)(sm8 + WXB_OFF);
    float* bias_sm = (float*)(sm8 + BIAS_OFF);

    uint32_t smem_u32;
    asm("{ .reg .u64 t; cvta.to.shared.u64 t, %1; cvt.u32.u64 %0, t; }"
        : "=r"(smem_u32) : "l"(sm8));

    const int tid     = threadIdx.x;
    const int warp    = tid >> 5;
    const int lane    = tid & 31;
    const int sid     = warp >> 3;      // stream 0/1
    const int sw      = warp & 7;       // stream-local warp: h [4sw, 4sw+4)
    const int stid    = tid & 255;      // stream-local thread
    const int ctarank = blockIdx.x & 7;
    const int clust   = blockIdx.x >> 3;
    const int h0      = ctarank * 32;
    const int b0s     = clust * 32 + sid * NB;

    const float* Wg[4] = {w_f, w_i, w_g, w_o};
    const float* Bg[4] = {b_f, b_i, b_g, b_o};

    if (tid < 128) {
        int g = tid >> 5, h = tid & 31;
        wxb_sm[g * 32 + h]  = Wg[g][(h0 + h) * 257];
        bias_sm[g * 32 + h] = Bg[g][h0 + h];
    }
    if (tid < 4) MBARRIER_INIT(smem_u32 + MBAR_OFF + tid * 8, 1);

    // Permuted layout:
    //  m-tile row r = h2*4 + gate   (h2 in 0..3, h_local = 4*mt + h2)
    //  K chunk kc covers h_src [16kc,16kc+16); within-chunk k_idx -> h offset:
    //  HOFF = {0,2,1,3,4,6,5,7,8,10,9,11,12,14,13,15}; thread column base
    //  d = ((lane>>1)&1)*4 + (lane&1); cols = {d, d+2, d+8, d+10}.

    const int q    = lane >> 2;          // 0..7
    const int gidx = q & 3;              // this thread's gate in A rows
    const int h2l  = q >> 2;             // 0/1: h pair low index
    const int dcol = ((lane >> 1) & 1) * 4 + (lane & 1);

    // ---- build A-hi frags in regs (full K), A-lo into smem (warps 0..7)
    uint32_t ahi[64];
    {
        const float* row0 = Wg[gidx] + (h0 + 4 * sw + h2l) * 257 + 1;
        const float* row1 = Wg[gidx] + (h0 + 4 * sw + h2l + 2) * 257 + 1;
#pragma unroll
        for (int kc = 0; kc < 16; ++kc) {
            int base = kc * 16 + dcol;
            float v00 = row0[base],      v01 = row0[base + 2];
            float v10 = row1[base],      v11 = row1[base + 2];
            float v02 = row0[base + 8],  v03 = row0[base + 10];
            float v12 = row1[base + 8],  v13 = row1[base + 10];
            float h00 = __bfloat162float(__float2bfloat16(v00));
            float h01 = __bfloat162float(__float2bfloat16(v01));
            float h10 = __bfloat162float(__float2bfloat16(v10));
            float h11 = __bfloat162float(__float2bfloat16(v11));
            float h02 = __bfloat162float(__float2bfloat16(v02));
            float h03 = __bfloat162float(__float2bfloat16(v03));
            float h12 = __bfloat162float(__float2bfloat16(v12));
            float h13 = __bfloat162float(__float2bfloat16(v13));
            ahi[kc * 4 + 0] = pack2bf(h00, h01);
            ahi[kc * 4 + 1] = pack2bf(h10, h11);
            ahi[kc * 4 + 2] = pack2bf(h02, h03);
            ahi[kc * 4 + 3] = pack2bf(h12, h13);
            if (sid == 0) {
                uint4 lo4;
                lo4.x = pack2bf(v00 - h00, v01 - h01);
                lo4.y = pack2bf(v10 - h10, v11 - h11);
                lo4.z = pack2bf(v02 - h02, v03 - h03);
                lo4.w = pack2bf(v12 - h12, v13 - h13);
                *(uint4*)(sm8 + ALO_OFF + ((sw * 16 + kc) * 32 + lane) * 16) = lo4;
            }
        }
    }

    // ---- zero par=0 B images of both streams
    {
        uint4 z = make_uint4(0, 0, 0, 0);
        uint4* b00 = (uint4*)(sm8 + BIMG_OFF);
        uint4* b10 = (uint4*)(sm8 + BIMG_OFF + 2 * BIMG_BYTES);
        for (int i = tid; i < BIMG_BYTES / 16; i += LSTM_THREADS) {
            b00[i] = z; b10[i] = z;
        }
    }
    __syncthreads();
    if (stid == 0) MBAR_EXPECT_TX(smem_u32 + MBAR_OFF + (sid * 2 + 1) * 8, TX_BYTES);
    __syncthreads();
    CLUSTER_SYNC_();

    // ---- per-thread epilogue constants (post-butterfly ownership)
    const int b0sel = (lane >> 2) & 1;   // gate bit0
    const int b1sel = (lane >> 3) & 1;   // gate bit1
    const int b_final = 2 * (lane & 3) + b0sel + 8 * b1sel;   // batch 0..15
    const int hl = 4 * sw + h2l;                               // h pair low
    // push offset: pair (h0+hl, h0+hl+2)
    const int hg  = h0 + hl;
    const int kcp = hg >> 4;
    const int dd  = hg & 15;
    const int j2p = ((dd >> 2) << 1) | (dd & 1);
    const uint32_t ep_off = (uint32_t)(b_final * ROW_BYTES + kcp * 64
                                       + (j2p & 3) * 16 + ((j2p >> 2) ? 8 : 0));

    uint32_t dstA[8], mbA[8];
#pragma unroll
    for (int r = 0; r < 8; ++r) {
        uint32_t dl = smem_u32 + BIMG_OFF + (sid * 2 + 1) * BIMG_BYTES + ep_off;
        uint32_t ml = smem_u32 + MBAR_OFF + (sid * 2 + 1) * 8;
        asm("mapa.shared::cluster.u32 %0, %1, %2;" : "=r"(dstA[r]) : "r"(dl), "r"(r));
        asm("mapa.shared::cluster.u32 %0, %1, %2;" : "=r"(mbA[r])  : "r"(ml), "r"(r));
    }

    const float wxf = wxb_sm[0 * 32 + hl], bif = bias_sm[0 * 32 + hl];
    const float wxi = wxb_sm[1 * 32 + hl], bii = bias_sm[1 * 32 + hl];
    const float wxg = wxb_sm[2 * 32 + hl], big = bias_sm[2 * 32 + hl];
    const float wxo = wxb_sm[3 * 32 + hl], bio = bias_sm[3 * 32 + hl];
    const float wxf2 = wxb_sm[0 * 32 + hl + 2], bif2 = bias_sm[0 * 32 + hl + 2];
    const float wxi2 = wxb_sm[1 * 32 + hl + 2], bii2 = bias_sm[1 * 32 + hl + 2];
    const float wxg2 = wxb_sm[2 * 32 + hl + 2], big2 = bias_sm[2 * 32 + hl + 2];
    const float wxo2 = wxb_sm[3 * 32 + hl + 2], bio2 = bias_sm[3 * 32 + hl + 2];
    const float* xptr = xfeat + (b0s + b_final) * SEQ;

    float cx[2] = {0.f, 0.f};

#pragma unroll 1
    for (int t = 0; t < SEQ; ++t) {
        const int par = t & 1;
        const uint32_t ph = (uint32_t)(((t - 1) >> 1) & 1);
        const uint32_t mb_rd = smem_u32 + MBAR_OFF + (sid * 2 + par) * 8;

        float xb = __ldg(xptr + t);   // hidden behind the wait + MMA

        if (t > 0) MBAR_WAIT_PARITY(mb_rd, ph);
        // re-arm this buffer's next phase BEFORE our own pushes (same thread
        // later pushes; peers' next-phase pushes causally require ours)
        if (stid == 0) MBAR_EXPECT_TX(mb_rd, TX_BYTES);

        // ---- MMA: this stream's B image; full K per warp, 2 n-tiles
        const uint8_t* bimg = sm8 + BIMG_OFF + (sid * 2 + par) * BIMG_BYTES;
        float acc0[4] = {0.f,0.f,0.f,0.f};
        float acc1[4] = {0.f,0.f,0.f,0.f};
        {
            const uint8_t* bp = bimg + (lane >> 2) * ROW_BYTES + (lane & 3) * 16;
            const uint4* alp = (const uint4*)(sm8 + ALO_OFF) + (sw * 16) * 32 + lane;
#pragma unroll
            for (int kc = 0; kc < 16; ++kc) {
                uint4 p0 = *(const uint4*)(bp + kc * 64);
                uint4 p1 = *(const uint4*)(bp + 8 * ROW_BYTES + kc * 64);
                uint4 al = alp[kc * 32];
                mma16816(acc0, ahi + kc * 4, p0.x, p0.z);          // Whi*Hhi
                mma16816(acc1, ahi + kc * 4, p1.x, p1.z);
                mma16816(acc0, (const uint32_t*)&al, p0.x, p0.z);  // Wlo*Hhi
                mma16816(acc1, (const uint32_t*)&al, p1.x, p1.z);
                mma16816(acc0, ahi + kc * 4, p0.y, p0.w);          // Whi*Hlo
                mma16816(acc1, ahi + kc * 4, p1.y, p1.w);
            }
        }

        // ---- butterfly transpose: gather 4 gates of (hl, hl+2) x b_final
        // V[hI][bI]: bI 0=2s,1=2s+1,2=2s+8,3=2s+9
        // round 1 (xor 4, gate bit0)
        float sA = b0sel ? acc0[0] : acc0[1];
        float sB = b0sel ? acc0[2] : acc0[3];
        float sC = b0sel ? acc1[0] : acc1[1];
        float sD = b0sel ? acc1[2] : acc1[3];
        float rA = __shfl_xor_sync(0xffffffffu, sA, 4);
        float rB = __shfl_xor_sync(0xffffffffu, sB, 4);
        float rC = __shfl_xor_sync(0xffffffffu, sC, 4);
        float rD = __shfl_xor_sync(0xffffffffu, sD, 4);
        float kA = b0sel ? acc0[1] : acc0[0];
        float kB = b0sel ? acc0[3] : acc0[2];
        float kC = b0sel ? acc1[1] : acc1[0];
        float kD = b0sel ? acc1[3] : acc1[2];
        // canonical even/odd gate, slots l (bI bit1=0) / h (bit1=1)
        float E0l = b0sel ? rA : kA,  O0l = b0sel ? kA : rA;
        float E1l = b0sel ? rB : kB,  O1l = b0sel ? kB : rB;
        float E0h = b0sel ? rC : kC,  O0h = b0sel ? kC : rC;
        float E1h = b0sel ? rD : kD,  O1h = b0sel ? kD : rD;
        // round 2 (xor 8, gate bit1)
        float s0 = b1sel ? E0l : E0h;
        float s1 = b1sel ? E1l : E1h;
        float s2 = b1sel ? O0l : O0h;
        float s3 = b1sel ? O1l : O1h;
        float r0 = __shfl_xor_sync(0xffffffffu, s0, 8);
        float r1 = __shfl_xor_sync(0xffffffffu, s1, 8);
        float r2 = __shfl_xor_sync(0xffffffffu, s2, 8);
        float r3 = __shfl_xor_sync(0xffffffffu, s3, 8);
        float kE0 = b1sel ? E0h : E0l;
        float kE1 = b1sel ? E1h : E1l;
        float kO0 = b1sel ? O0h : O0l;
        float kO1 = b1sel ? O1h : O1l;
        float Ff0 = b1sel ? r0 : kE0,  Fg0 = b1sel ? kE0 : r0;  // gates f,g (hI0)
        float Ff1 = b1sel ? r1 : kE1,  Fg1 = b1sel ? kE1 : r1;  // (hI1)
        float Fi0 = b1sel ? r2 : kO0,  Fo0 = b1sel ? kO0 : r2;  // gates i,o
        float Fi1 = b1sel ? r3 : kO1,  Fo1 = b1sel ? kO1 : r3;

        // ---- epilogue (in-warp): cx/hx for (hl, hl+2) x b_final
        float vout0, vout1;
        {
            float pf = Ff0 + fmaf(wxf, xb, bif);
            float pi = Fi0 + fmaf(wxi, xb, bii);
            float pg = Fg0 + fmaf(wxg, xb, big);
            float po = Fo0 + fmaf(wxo, xb, bio);
            float f  = fast_sigmoid(pf);
            float ii = fast_sigmoid(pi);
            float gg = fast_tanh(pg);
            float oo = fast_sigmoid(po);
            cx[0] = fmaf(f, cx[0], ii * gg);
            vout0 = oo * fast_tanh(cx[0]);
        }
        {
            float pf = Ff1 + fmaf(wxf2, xb, bif2);
            float pi = Fi1 + fmaf(wxi2, xb, bii2);
            float pg = Fg1 + fmaf(wxg2, xb, big2);
            float po = Fo1 + fmaf(wxo2, xb, bio2);
            float f  = fast_sigmoid(pf);
            float ii = fast_sigmoid(pi);
            float gg = fast_tanh(pg);
            float oo = fast_sigmoid(po);
            cx[1] = fmaf(f, cx[1], ii * gg);
            vout1 = oo * fast_tanh(cx[1]);
        }

        // ---- push: 8B packet = hi(hl,hl+2), lo(hl,hl+2) for b_final
        {
            float f0h = __bfloat162float(__float2bfloat16(vout0));
            float f1h = __bfloat162float(__float2bfloat16(vout1));
            uint32_t hw = pack2bf(f0h, f1h);
            uint32_t lw = pack2bf(vout0 - f0h, vout1 - f1h);
            uint64_t pkt = (uint64_t)hw | ((uint64_t)lw << 32);

            const uint32_t dadj = par ? (uint32_t)BIMG_BYTES : 0u;  // buf=par^1
            const uint32_t madj = par ? 8u : 0u;
#pragma unroll
            for (int r = 0; r < 8; ++r)
                ST_ASYNC_B64(dstA[r] - dadj, pkt, mbA[r] - madj);

            if (t == SEQ - 1) {
                g_hxf32[(b0s + b_final) * HID + h0 + hl]     = vout0;
                g_hxf32[(b0s + b_final) * HID + h0 + hl + 2] = vout1;
            }
        }
    }

    FENCE_CLUSTER_();
    CLUSTER_SYNC_();

    // ---- head (rank-0 CTA): logits for the cluster's 32 batches
    if (ctarank == 0 && tid < 256) {
        const int bb   = tid >> 3;
        const int part = tid & 7;
        const float* src = g_hxf32 + (clust * 32 + bb) * HID + part * 32;
        float s = 0.0f;
#pragma unroll
        for (int kk = 0; kk < 32; ++kk)
            s = fmaf(src[kk], __ldg(w_head + part * 32 + kk), s);
        s += __shfl_xor_sync(0xffffffffu, s, 4);
        s += __shfl_xor_sync(0xffffffffu, s, 2);
        s += __shfl_xor_sync(0xffffffffu, s, 1);
        if (part == 0) logits[clust * 32 + bb] = s + __ldg(b_head);
    }
}

// ======================= launch ===========================================

extern "C" void kernel_launch(void* const* d_in, const int* in_sizes, int n_in,
                              void* d_out, int out_size)
{
    const float* x      = (const float*)d_in[0];
    const float* w1     = (const float*)d_in[1];
    const float* b1     = (const float*)d_in[2];
    const float* w2     = (const float*)d_in[3];
    const float* b2     = (const float*)d_in[4];
    const float* w3     = (const float*)d_in[5];
    const float* b3     = (const float*)d_in[6];
    const float* w4     = (const float*)d_in[7];
    const float* b4     = (const float*)d_in[8];
    const float* w5     = (const float*)d_in[9];
    const float* b5     = (const float*)d_in[10];
    const float* w6     = (const float*)d_in[11];
    const float* b6     = (const float*)d_in[12];
    const float* w7     = (const float*)d_in[13];
    const float* b7     = (const float*)d_in[14];
    const float* w_f    = (const float*)d_in[15];
    const float* b_f    = (const float*)d_in[16];
    const float* w_i    = (const float*)d_in[17];
    const float* b_i    = (const float*)d_in[18];
    const float* w_g    = (const float*)d_in[19];
    const float* b_g    = (const float*)d_in[20];
    const float* w_o    = (const float*)d_in[21];
    const float* b_o    = (const float*)d_in[22];
    const float* w_head = (const float*)d_in[23];
    const float* b_head = (const float*)d_in[24];

    float* out = (float*)d_out;

    cnn_kernel<<<(BATCH * SEQ) / 256, 256>>>(x, w1, b1, w2, b2, w3, b3, w4, b4,
                                             w5, b5, w6, b6, w7, b7, out);

    cudaFuncSetAttribute(lstm_kernel, cudaFuncAttributeMaxDynamicSharedMemorySize,
                         SMEM_BYTES);
    lstm_kernel<<<LSTM_CTAS, LSTM_THREADS, SMEM_BYTES>>>(
        out, w_f, b_f, w_i, b_i, w_g, b_g, w_o, b_o, w_head, b_head,
        out + BATCH * SEQ);
}

// round 15
// speedup vs baseline: 1.5016x; 1.5016x over previous
#include <cuda_runtime.h>
#include <cuda_bf16.h>
#include <cstdint>
#include <math.h>

// ---------------------------------------------------------------------------
// HybridQCNNQLSTM : B=256, S=1024, H=256
//   Stage 1: per-element MLP 1->16->16->12->8->4->4 (tanh) -> 1 (linear)
//   Stage 2: LSTM via mma.sync m16n8k16 bf16 (hi/lo split x3, fp32 acc)
//            16 clusters x 8 CTAs (128 SMs), TWO warp-specialized streams
//            per CTA (N=8 batches each). st.async DSMEM exchange with
//            mbarrier complete_tx (R12 protocol, halved per-chain work).
//   out = [cnn_features (B*S) | logits (B)]
// ---------------------------------------------------------------------------

#define BATCH 256
#define SEQ   1024
#define HID   256

// ======================= Stage 1: CNN MLP kernel ===========================

template<int DIN, int DOUT>
__device__ __forceinline__ void layer_tanh(const float* __restrict__ w,
                                           const float* __restrict__ b,
                                           const float* in, float* out) {
#pragma unroll
    for (int o = 0; o < DOUT; ++o) {
        float s = b[o];
#pragma unroll
        for (int i = 0; i < DIN; ++i) s = fmaf(w[o * DIN + i], in[i], s);
        out[o] = tanhf(s);
    }
}

__global__ void __launch_bounds__(256) cnn_kernel(
    const float* __restrict__ x,
    const float* __restrict__ w1, const float* __restrict__ b1,
    const float* __restrict__ w2, const float* __restrict__ b2,
    const float* __restrict__ w3, const float* __restrict__ b3,
    const float* __restrict__ w4, const float* __restrict__ b4,
    const float* __restrict__ w5, const float* __restrict__ b5,
    const float* __restrict__ w6, const float* __restrict__ b6,
    const float* __restrict__ w7, const float* __restrict__ b7,
    float* __restrict__ out)
{
    __shared__ float ws[673];
    const int tid = threadIdx.x;
    {
        const float* srcs[14] = {w1,b1,w2,b2,w3,b3,w4,b4,w5,b5,w6,b6,w7,b7};
        const int    lens[14] = {16,16,256,16,192,12,96,8,32,4,16,4,4,1};
        int off = 0;
        for (int s = 0; s < 14; ++s) {
            for (int i = tid; i < lens[s]; i += 256) ws[off + i] = srcs[s][i];
            off += lens[s];
        }
    }
    __syncthreads();

    const int e = blockIdx.x * 256 + tid;
    float v = x[e];
    float h1[16], h2[16], h3[12], h4[8], h5[4], h6[4];
    layer_tanh<1, 16>(ws + 0,   ws + 16,  &v, h1);
    layer_tanh<16,16>(ws + 32,  ws + 288, h1, h2);
    layer_tanh<16,12>(ws + 304, ws + 496, h2, h3);
    layer_tanh<12, 8>(ws + 508, ws + 604, h3, h4);
    layer_tanh<8,  4>(ws + 612, ws + 644, h4, h5);
    layer_tanh<4,  4>(ws + 648, ws + 664, h5, h6);
    float o = ws[672];
#pragma unroll
    for (int i = 0; i < 4; ++i) o = fmaf(ws[668 + i], h6[i], o);
    out[e] = o;
}

// ======================= Stage 2: LSTM (dual-stream, st.async, N=8) ========

#define NB           8                      // batches per stream
#define NCLUST       16
#define LSTM_CTAS    128
#define LSTM_THREADS 512

#define ROW_BYTES   1088                    // 16 kc * 64B + 64B pad
#define BIMG_BYTES  (NB * ROW_BYTES)        // 8704
#define TX_BYTES    8192u                   // real data per image per phase
#define RED_STR     10
#define RED_BYTES   (128 * RED_STR * 4)     // 5120

// smem byte offsets
#define ALO_OFF    0                        // A-lo frags: 8*16*32*16 = 65536
#define BIMG_OFF   65536                    // 4 images (sid*2+buf) = 34816
#define RED_OFF    100352                   // 2 * 5120 = 10240
#define WXB_OFF    110592                   // [4][32] f32
#define BIAS_OFF   111104
#define XS_OFF     111616                   // 2 * 8 f32
#define MBAR_OFF   111744                   // 4 x 8B
#define SMEM_BYTES 111872

__device__ float g_hxf32[BATCH * HID];

__device__ __forceinline__ float fast_sigmoid(float v) {
    return __fdividef(1.0f, 1.0f + __expf(-v));
}
__device__ __forceinline__ float fast_tanh(float v) {
    return 1.0f - __fdividef(2.0f, __expf(2.0f * v) + 1.0f);
}
__device__ __forceinline__ uint32_t pack2bf(float lo, float hi) {
    __nv_bfloat162 t = __floats2bfloat162_rn(lo, hi);
    return *(uint32_t*)&t;
}

__device__ __forceinline__ void mma16816(float* c, const uint32_t* a,
                                         uint32_t b0, uint32_t b1) {
    asm volatile(
        "mma.sync.aligned.m16n8k16.row.col.f32.bf16.bf16.f32 "
        "{%0,%1,%2,%3}, {%4,%5,%6,%7}, {%8,%9}, {%0,%1,%2,%3};"
        : "+f"(c[0]), "+f"(c[1]), "+f"(c[2]), "+f"(c[3])
        : "r"(a[0]), "r"(a[1]), "r"(a[2]), "r"(a[3]), "r"(b0), "r"(b1));
}

#define CLUSTER_SYNC_() do { \
    asm volatile("barrier.cluster.arrive.aligned;" ::: "memory"); \
    asm volatile("barrier.cluster.wait.aligned;"   ::: "memory"); \
} while (0)

#define FENCE_CLUSTER_() asm volatile("fence.acq_rel.cluster;" ::: "memory")

#define BAR_STREAM(sid) \
    asm volatile("bar.sync %0, 256;" :: "r"((sid) + 1) : "memory")

#define MBARRIER_INIT(mbar, cnt) \
    asm volatile("mbarrier.init.shared.b64 [%0], %1;" \
        :: "r"((uint32_t)(mbar)), "r"((uint32_t)(cnt)) : "memory")

#define MBAR_EXPECT_TX(mbar, bytes) \
    asm volatile("mbarrier.arrive.expect_tx.shared.b64 _, [%0], %1;" \
        :: "r"((uint32_t)(mbar)), "r"((uint32_t)(bytes)) : "memory")

#define MBAR_WAIT_PARITY(mbar, par) do { \
    uint32_t _m = (uint32_t)(mbar); uint32_t _p = (uint32_t)(par); uint32_t _d; \
    asm volatile("{\n\t.reg .pred p;\n\t" \
        "mbarrier.try_wait.parity.acquire.cta.shared::cta.b64 p, [%1], %2;\n\t" \
        "selp.b32 %0, 1, 0, p;\n\t}" : "=r"(_d) : "r"(_m), "r"(_p) : "memory"); \
    if (!_d) { \
        asm volatile("{\n\t.reg .pred P1;\n\t" \
            "WL_%=:\n\t" \
            "mbarrier.try_wait.parity.acquire.cta.shared::cta.b64 P1, [%0], %1, 0x989680;\n\t" \
            "@P1 bra.uni WD_%=;\n\t" \
            "bra.uni WL_%=;\n\t" \
            "WD_%=:\n\t}" :: "r"(_m), "r"(_p) : "memory"); \
    } \
} while(0)

// async DSMEM store: 8B payload + transaction completion on remote mbarrier
#define ST_ASYNC_B64(daddr, val, mbaddr) \
    asm volatile("st.async.weak.shared::cluster.mbarrier::complete_tx::bytes.b64 [%0], %1, [%2];" \
        :: "r"((uint32_t)(daddr)), "l"(val), "r"((uint32_t)(mbaddr)) : "memory")

__global__ void __launch_bounds__(LSTM_THREADS, 1) __cluster_dims__(8, 1, 1)
lstm_kernel(const float* __restrict__ xfeat,
            const float* __restrict__ w_f, const float* __restrict__ b_f,
            const float* __restrict__ w_i, const float* __restrict__ b_i,
            const float* __restrict__ w_g, const float* __restrict__ b_g,
            const float* __restrict__ w_o, const float* __restrict__ b_o,
            const float* __restrict__ w_head, const float* __restrict__ b_head,
            float* __restrict__ logits)
{
    extern __shared__ __align__(16) uint8_t sm8[];
    float* wxb_sm  = (float*)(sm8 + WXB_OFF);
    float* bias_sm = (float*)(sm8 + BIAS_OFF);

    uint32_t smem_u32;
    asm("{ .reg .u64 t; cvta.to.shared.u64 t, %1; cvt.u32.u64 %0, t; }"
        : "=r"(smem_u32) : "l"(sm8));

    const int tid     = threadIdx.x;
    const int warp    = tid >> 5;
    const int lane    = tid & 31;
    const int sid     = warp >> 3;      // stream 0/1
    const int sw      = warp & 7;       // stream-local warp = mrow
    const int stid    = tid & 255;      // stream-local thread
    const int ctarank = blockIdx.x & 7;
    const int clust   = blockIdx.x >> 3;
    const int h0      = ctarank * 32;
    const int b0s     = clust * 16 + sid * NB;

    float* redS = (float*)(sm8 + RED_OFF + sid * RED_BYTES);
    float* xsS  = (float*)(sm8 + XS_OFF) + sid * NB;

    const float* Wg[4] = {w_f, w_i, w_g, w_o};
    const float* Bg[4] = {b_f, b_i, b_g, b_o};

    if (tid < 128) {
        int g = tid >> 5, h = tid & 31;
        wxb_sm[g * 32 + h]  = Wg[g][(h0 + h) * 257];
        bias_sm[g * 32 + h] = Bg[g][h0 + h];
    }
    if (tid < 4) MBARRIER_INIT(smem_u32 + MBAR_OFF + tid * 8, 1);

    // ---- build A-hi frags in regs (full K), A-lo into smem (stream 0 writes)
    uint32_t ahi[64];
    {
        const int r0 = sw * 16 + (lane >> 2);
        const int r1 = r0 + 8;
        const float* row0 = Wg[r0 >> 5] + (h0 + (r0 & 31)) * 257 + 1;
        const float* row1 = Wg[r1 >> 5] + (h0 + (r1 & 31)) * 257 + 1;
        const int kb = (lane & 3) * 2;
#pragma unroll
        for (int kc = 0; kc < 16; ++kc) {
            int k0 = kc * 16 + kb;
            float v00 = row0[k0],     v01 = row0[k0 + 1];
            float v10 = row1[k0],     v11 = row1[k0 + 1];
            float v02 = row0[k0 + 8], v03 = row0[k0 + 9];
            float v12 = row1[k0 + 8], v13 = row1[k0 + 9];
            float h00 = __bfloat162float(__float2bfloat16(v00));
            float h01 = __bfloat162float(__float2bfloat16(v01));
            float h10 = __bfloat162float(__float2bfloat16(v10));
            float h11 = __bfloat162float(__float2bfloat16(v11));
            float h02 = __bfloat162float(__float2bfloat16(v02));
            float h03 = __bfloat162float(__float2bfloat16(v03));
            float h12 = __bfloat162float(__float2bfloat16(v12));
            float h13 = __bfloat162float(__float2bfloat16(v13));
            ahi[kc * 4 + 0] = pack2bf(h00, h01);
            ahi[kc * 4 + 1] = pack2bf(h10, h11);
            ahi[kc * 4 + 2] = pack2bf(h02, h03);
            ahi[kc * 4 + 3] = pack2bf(h12, h13);
            if (sid == 0) {
                uint4 lo4;
                lo4.x = pack2bf(v00 - h00, v01 - h01);
                lo4.y = pack2bf(v10 - h10, v11 - h11);
                lo4.z = pack2bf(v02 - h02, v03 - h03);
                lo4.w = pack2bf(v12 - h12, v13 - h13);
                *(uint4*)(sm8 + ALO_OFF + ((sw * 16 + kc) * 32 + lane) * 16) = lo4;
            }
        }
    }

    // ---- zero par=0 B images of both streams
    {
        uint4 z = make_uint4(0, 0, 0, 0);
        uint4* b00 = (uint4*)(sm8 + BIMG_OFF);                   // sid0 buf0
        uint4* b10 = (uint4*)(sm8 + BIMG_OFF + 2 * BIMG_BYTES);  // sid1 buf0
        for (int i = tid; i < BIMG_BYTES / 16; i += LSTM_THREADS) {
            b00[i] = z; b10[i] = z;
        }
    }
    __syncthreads();
    // pre-loop expect for buffer 1 phase 0 (filled by pushes during t=0)
    if (stid == 0) MBAR_EXPECT_TX(smem_u32 + MBAR_OFF + (sid * 2 + 1) * 8, TX_BYTES);
    __syncthreads();
    CLUSTER_SYNC_();   // images, mbar inits+expect, A-lo visible cluster-wide

    // epilogue constants: 128 active threads/stream cover 8 b x 16 h-pairs
    const int ep_b  = (stid >> 4) & 7;  // 0..7
    const int ep_hp = stid & 15;
    const bool ep_on = (stid < 128);
    const int ep_kc = ctarank * 2 + (ep_hp >> 3);
    const int ep_j2 = ep_hp & 7;
    const int ep_c  = (ep_j2 < 4) ? ep_j2 : (ep_j2 - 4);
    const int ep_sl = (ep_j2 < 4) ? 0 : 8;
    const uint32_t ep_off = (uint32_t)(ep_b * ROW_BYTES + ep_kc * 64 + ep_c * 16 + ep_sl);

    // precompute remote data/mbar addresses for buf=1; buf=0 = -BIMG_BYTES/-8
    uint32_t dstA[8], mbA[8];
#pragma unroll
    for (int r = 0; r < 8; ++r) {
        uint32_t dl = smem_u32 + BIMG_OFF + (sid * 2 + 1) * BIMG_BYTES + ep_off;
        uint32_t ml = smem_u32 + MBAR_OFF + (sid * 2 + 1) * 8;
        asm("mapa.shared::cluster.u32 %0, %1, %2;" : "=r"(dstA[r]) : "r"(dl), "r"(r));
        asm("mapa.shared::cluster.u32 %0, %1, %2;" : "=r"(mbA[r])  : "r"(ml), "r"(r));
    }

    float cx[2] = {0.f, 0.f};

#pragma unroll 1
    for (int t = 0; t < SEQ; ++t) {
        const int par = t & 1;
        const uint32_t ph = (uint32_t)(((t - 1) >> 1) & 1);
        const uint32_t mb_rd = smem_u32 + MBAR_OFF + (sid * 2 + par) * 8;

        if (stid < NB) xsS[stid] = __ldg(xfeat + (b0s + stid) * SEQ + t);

        if (t > 0) MBAR_WAIT_PARITY(mb_rd, ph);
        // re-arm this buffer's next phase BEFORE our own pushes of this step
        if (stid == 0) MBAR_EXPECT_TX(mb_rd, TX_BYTES);

        // ---- MMA: this stream's B image; full K per warp, 1 n-tile (N=8)
        const uint8_t* bimg = sm8 + BIMG_OFF + (sid * 2 + par) * BIMG_BYTES;
        float acc0[4] = {0.f,0.f,0.f,0.f};
        {
            const uint8_t* bp = bimg + (lane >> 2) * ROW_BYTES + (lane & 3) * 16;
            const uint4* alp = (const uint4*)(sm8 + ALO_OFF) + (sw * 16) * 32 + lane;
#pragma unroll
            for (int kc = 0; kc < 16; ++kc) {
                uint4 p0 = *(const uint4*)(bp + kc * 64);
                uint4 al = alp[kc * 32];
                mma16816(acc0, ahi + kc * 4, p0.x, p0.z);          // Whi*Hhi
                mma16816(acc0, (const uint32_t*)&al, p0.x, p0.z);  // Wlo*Hhi
                mma16816(acc0, ahi + kc * 4, p0.y, p0.w);          // Whi*Hlo
            }
        }

        // ---- gate transpose into stream red
        {
            const int r0 = sw * 16 + (lane >> 2);
            const int c0 = (lane & 3) * 2;
            *(float2*)(redS + r0 * RED_STR + c0)       = make_float2(acc0[0], acc0[1]);
            *(float2*)(redS + (r0 + 8) * RED_STR + c0) = make_float2(acc0[2], acc0[3]);
        }
        BAR_STREAM(sid);

        // ---- epilogue: gates -> cx/hx -> st.async push into all 8 B[par^1]
        if (ep_on) {
            float xb = xsS[ep_b];
            float vout[2];
#pragma unroll
            for (int j = 0; j < 2; ++j) {
                int h = ep_hp * 2 + j;
                float pf = redS[(0*32 + h) * RED_STR + ep_b] + fmaf(wxb_sm[0*32+h], xb, bias_sm[0*32+h]);
                float pi = redS[(1*32 + h) * RED_STR + ep_b] + fmaf(wxb_sm[1*32+h], xb, bias_sm[1*32+h]);
                float pg = redS[(2*32 + h) * RED_STR + ep_b] + fmaf(wxb_sm[2*32+h], xb, bias_sm[2*32+h]);
                float po = redS[(3*32 + h) * RED_STR + ep_b] + fmaf(wxb_sm[3*32+h], xb, bias_sm[3*32+h]);
                float f  = fast_sigmoid(pf);
                float ii = fast_sigmoid(pi);
                float gg = fast_tanh(pg);
                float oo = fast_sigmoid(po);
                cx[j] = fmaf(f, cx[j], ii * gg);
                vout[j] = oo * fast_tanh(cx[j]);
            }
            float f0h = __bfloat162float(__float2bfloat16(vout[0]));
            float f1h = __bfloat162float(__float2bfloat16(vout[1]));
            uint32_t hw = pack2bf(f0h, f1h);
            uint32_t lw = pack2bf(vout[0] - f0h, vout[1] - f1h);
            uint64_t pkt = (uint64_t)hw | ((uint64_t)lw << 32);

            const uint32_t dadj = par ? (uint32_t)BIMG_BYTES : 0u;  // buf=par^1
            const uint32_t madj = par ? 8u : 0u;
#pragma unroll
            for (int r = 0; r < 8; ++r)
                ST_ASYNC_B64(dstA[r] - dadj, pkt, mbA[r] - madj);

            if (t == SEQ - 1)
                *(float2*)(g_hxf32 + (b0s + ep_b) * HID + h0 + ep_hp * 2) =
                    make_float2(vout[0], vout[1]);
        }
        // destination mbarrier byte-count provides completion + backpressure
    }

    FENCE_CLUSTER_();
    CLUSTER_SYNC_();

    // ---- head (rank-0 CTA): logits for the cluster's 16 batches
    if (ctarank == 0 && tid < 128) {
        const int bb   = tid >> 3;   // 0..15
        const int part = tid & 7;    // 0..7
        const float* src = g_hxf32 + (clust * 16 + bb) * HID + part * 32;
        float s = 0.0f;
#pragma unroll
        for (int kk = 0; kk < 32; ++kk)
            s = fmaf(src[kk], __ldg(w_head + part * 32 + kk), s);
        s += __shfl_xor_sync(0xffffffffu, s, 4);
        s += __shfl_xor_sync(0xffffffffu, s, 2);
        s += __shfl_xor_sync(0xffffffffu, s, 1);
        if (part == 0) logits[clust * 16 + bb] = s + __ldg(b_head);
    }
}

// ======================= launch ===========================================

extern "C" void kernel_launch(void* const* d_in, const int* in_sizes, int n_in,
                              void* d_out, int out_size)
{
    const float* x      = (const float*)d_in[0];
    const float* w1     = (const float*)d_in[1];
    const float* b1     = (const float*)d_in[2];
    const float* w2     = (const float*)d_in[3];
    const float* b2     = (const float*)d_in[4];
    const float* w3     = (const float*)d_in[5];
    const float* b3     = (const float*)d_in[6];
    const float* w4     = (const float*)d_in[7];
    const float* b4     = (const float*)d_in[8];
    const float* w5     = (const float*)d_in[9];
    const float* b5     = (const float*)d_in[10];
    const float* w6     = (const float*)d_in[11];
    const float* b6     = (const float*)d_in[12];
    const float* w7     = (const float*)d_in[13];
    const float* b7     = (const float*)d_in[14];
    const float* w_f    = (const float*)d_in[15];
    const float* b_f    = (const float*)d_in[16];
    const float* w_i    = (const float*)d_in[17];
    const float* b_i    = (const float*)d_in[18];
    const float* w_g    = (const float*)d_in[19];
    const float* b_g    = (const float*)d_in[20];
    const float* w_o    = (const float*)d_in[21];
    const float* b_o    = (const float*)d_in[22];
    const float* w_head = (const float*)d_in[23];
    const float* b_head = (const float*)d_in[24];

    float* out = (float*)d_out;

    cnn_kernel<<<(BATCH * SEQ) / 256, 256>>>(x, w1, b1, w2, b2, w3, b3, w4, b4,
                                             w5, b5, w6, b6, w7, b7, out);

    cudaFuncSetAttribute(lstm_kernel, cudaFuncAttributeMaxDynamicSharedMemorySize,
                         SMEM_BYTES);
    lstm_kernel<<<LSTM_CTAS, LSTM_THREADS, SMEM_BYTES>>>(
        out, w_f, b_f, w_i, b_i, w_g, b_g, w_o, b_o, w_head, b_head,
        out + BATCH * SEQ);
}